// round 13
// baseline (speedup 1.0000x reference)
#include <cuda_runtime.h>
#include <stdint.h>

#define Bn 64
#define Cc 64
#define Hh 56
#define Ww 56
#define Pp 64
#define HW (Hh*Ww)        // 3136
#define CHW (Cc*HW)       // 200704
#define PIX (Bn*HW)       // 200704
#define PADW 58
#define PADHW (58*58)     // 3364
#define NPIX 4
#define GPR (Ww/NPIX)     // 14
#define GROUPS (PIX/NPIX) // 50176  (= 32 * 1568 exactly)
#define PSPLIT 4
#define PPT (Pp/PSPLIT)   // 16 output channels per thread

// ---- device scratch (statically zero-initialized; border of g_amask stays 0) ----
__device__ unsigned long long g_amask[Bn*PADHW];   // padded per-pixel sign masks (~1.7MB)
__device__ uint4  g_w4[Pp*9];     // per (p,tap): (pw_lo, vm_lo, pw_hi, vm_hi)
__device__ float  g_basef[9*Pp];  // per (border-case, p): base constant (as float)
__device__ float4 g_epi[Pp];      // A=scale*inv, B=beta-mean*inv+bias1, alpha, bias2
__device__ int    g_zero_cnt;
__device__ int    g_zero_list[4096];

// ---------------- prep: one block per output channel p; ballot-built masks ----------------
__global__ void prep_kernel(const float* __restrict__ w,
                            const float* __restrict__ gamma,
                            const float* __restrict__ beta,
                            const float* __restrict__ rmean,
                            const float* __restrict__ rvar,
                            const float* __restrict__ bias1,
                            const float* __restrict__ alpha,
                            const float* __restrict__ bias2) {
    int p = blockIdx.x;
    int c = threadIdx.x;            // 0..63 (one input channel per thread)
    int lane = c & 31, half = c >> 5;
    if (p == 0 && c == 0) g_zero_cnt = 0;   // init (prep runs before binarize)

    __shared__ unsigned s_pw[2][9], s_vm[2][9];
    __shared__ float s_abs[64];

    const float* wp = w + (size_t)p*(Cc*9) + (size_t)c*9;
    float wv[9], sa = 0.f;
    #pragma unroll
    for (int t = 0; t < 9; t++) { wv[t] = __ldg(wp + t); sa += fabsf(wv[t]); }
    s_abs[c] = sa;
    #pragma unroll
    for (int t = 0; t < 9; t++) {
        unsigned bp = __ballot_sync(0xffffffffu, wv[t] > 0.f);
        unsigned bv = __ballot_sync(0xffffffffu, wv[t] != 0.f);
        if (lane == 0) { s_pw[half][t] = bp; s_vm[half][t] = bv; }
    }
    __syncthreads();
    if (c != 0) return;

    float sabs = 0.f;
    for (int i = 0; i < 64; i++) sabs += s_abs[i];
    float scale = sabs * (1.0f / (float)(Cc*9));

    int nv[9], ppw[9];
    #pragma unroll
    for (int t = 0; t < 9; t++) {
        uint4 v;
        v.x = s_pw[0][t]; v.y = s_vm[0][t];
        v.z = s_pw[1][t]; v.w = s_vm[1][t];
        g_w4[p*9 + t] = v;
        nv[t]  = __popc(v.y) + __popc(v.w);
        ppw[t] = __popc(v.x) + __popc(v.z);
    }
    // conv = 2*acc - base[case]; valid tap contributes nv, padded tap 2*popc(pw)
    #pragma unroll
    for (int cs = 0; cs < 9; cs++) {
        int ch = cs / 3, cw = cs % 3;
        int base = 0;
        #pragma unroll
        for (int t = 0; t < 9; t++) {
            int kh = t / 3, kw = t % 3;
            bool invalid = (ch==0 && kh==0) || (ch==2 && kh==2) ||
                           (cw==0 && kw==0) || (cw==2 && kw==2);
            base += invalid ? 2*ppw[t] : nv[t];
        }
        g_basef[cs*Pp + p] = (float)base;
    }
    float inv = gamma[p] / sqrtf(rvar[p] + 1e-5f);
    float4 e;
    e.x = scale * inv;
    e.y = beta[p] - rmean[p]*inv + bias1[p];
    e.z = alpha[p];
    e.w = bias2[p];
    g_epi[p] = e;
}

// ---------------- binarize: 4 threads per pixel-quad (16 channels each) ----------------
__global__ __launch_bounds__(256)
void binarize_kernel(const float* __restrict__ x, const float* __restrict__ bias0) {
    int tid  = blockIdx.x*blockDim.x + threadIdx.x;   // 0 .. PIX-1 exactly
    int quad = tid >> 2;
    int cg   = tid & 3;                               // channel group of 16
    int b  = quad / (HW/4);
    int r4 = quad % (HW/4);
    int r  = r4 * 4;
    const float4* xp = (const float4*)(x + (size_t)b*CHW) + r4 + (size_t)(cg*16)*(HW/4);

    unsigned bits[4] = {0,0,0,0};
    bool anyzero = false;
    #pragma unroll
    for (int i = 0; i < 16; i++) {
        float bb = __ldg(bias0 + cg*16 + i);
        float4 v = __ldg(xp + (size_t)i*(HW/4));
        v.x += bb; v.y += bb; v.z += bb; v.w += bb;
        anyzero |= (v.x == 0.f) | (v.y == 0.f) | (v.z == 0.f) | (v.w == 0.f);
        bits[0] |= (unsigned)(v.x < 0.f) << i;
        bits[1] |= (unsigned)(v.y < 0.f) << i;
        bits[2] |= (unsigned)(v.z < 0.f) << i;
        bits[3] |= (unsigned)(v.w < 0.f) << i;
    }
    if (anyzero) {  // rare exact-zero: queue exact indices for fixup
        #pragma unroll
        for (int i = 0; i < 16; i++) {
            int c = cg*16 + i;
            float bb = __ldg(bias0 + c);
            float4 v = __ldg(xp + (size_t)i*(HW/4));
            float vv[4] = {v.x+bb, v.y+bb, v.z+bb, v.w+bb};
            for (int k = 0; k < 4; k++)
                if (vv[k] == 0.f) {
                    int s = atomicAdd(&g_zero_cnt, 1);
                    if (s < 4096) g_zero_list[s] = b*CHW + c*HW + (r+k);
                }
        }
    }
    unsigned sh = (cg & 1) * 16;
    int h = r / Ww, w_ = r % Ww;   // 4 pixels in same row (Ww % 4 == 0)
    unsigned long long* dst = g_amask + b*PADHW + (h+1)*PADW + (w_+1);
    #pragma unroll
    for (int k = 0; k < 4; k++) {
        unsigned v = bits[k] << sh;
        v |= __shfl_xor_sync(0xffffffffu, v, 1);        // merge halves of the 32-bit word
        unsigned other = __shfl_xor_sync(0xffffffffu, v, 2); // lo <-> hi exchange
        if (cg == 0)
            dst[k] = (unsigned long long)v | ((unsigned long long)other << 32);
    }
}

__global__ void noop_kernel() {}   // keeps conv in the profiled 4th launch slot

__device__ __forceinline__ unsigned xor3(unsigned a, unsigned b, unsigned c) {
    return a ^ b ^ c;
}
__device__ __forceinline__ unsigned maj3(unsigned a, unsigned b, unsigned c) {
    return (a & b) | (c & (a | b));
}

// ---------------- conv: CSA popcount ternary conv, uint4 weights, prefetch-2 ----------------
// Block = 4 warps; warp = psub (16 output channels), lane = pixel-quad.
__global__ __launch_bounds__(128, 5)
void conv_kernel(const float* __restrict__ x, float* __restrict__ out) {
    __shared__ uint4  s_w4[Pp*9];
    __shared__ float  s_basef[9*Pp];
    __shared__ float4 s_epi[Pp];
    for (int i = threadIdx.x; i < Pp*9; i += blockDim.x) s_w4[i]   = g_w4[i];
    for (int i = threadIdx.x; i < 9*Pp; i += blockDim.x) s_basef[i] = g_basef[i];
    for (int i = threadIdx.x; i < Pp;   i += blockDim.x) s_epi[i]   = g_epi[i];
    __syncthreads();

    int lane = threadIdx.x & 31;
    int psub = threadIdx.x >> 5;            // warp id = output-channel subset
    int g    = blockIdx.x * 32 + lane;      // pixel-quad (grid exact: 1568*32 = GROUPS)
    int b  = g / (Hh*GPR);
    int r  = g % (Hh*GPR);
    int h  = r / GPR;
    int w0 = (r % GPR) * NPIX;

    // 3 rows x 6 cols of padded neighbor masks, split into 32-bit halves
    unsigned mlo[3][6], mhi[3][6];
    const unsigned long long* am = g_amask + b*PADHW;
    #pragma unroll
    for (int ri = 0; ri < 3; ri++)
        #pragma unroll
        for (int ci = 0; ci < 6; ci++) {
            unsigned long long v = __ldg(am + (h+ri)*PADW + (w0+ci));
            mlo[ri][ci] = (unsigned)v;
            mhi[ri][ci] = (unsigned)(v >> 32);
        }

    int ch    = (h == 0) ? 0 : ((h == Hh-1) ? 2 : 1);
    int caseM = ch*3 + 1;
    int caseL = ch*3 + ((w0 == 0) ? 0 : 1);
    int caseR = ch*3 + ((w0 + NPIX - 1 == Ww-1) ? 2 : 1);

    size_t obase = (size_t)b*CHW + (size_t)h*Ww + w0;
    int p0 = psub * PPT;

    // residual prefetch ring, distance 2
    float4 resbuf[2];
    resbuf[0] = __ldg((const float4*)(x + obase + (size_t)(p0+0)*HW));
    resbuf[1] = __ldg((const float4*)(x + obase + (size_t)(p0+1)*HW));

    #pragma unroll 2
    for (int i = 0; i < PPT; i++) {
        int p = p0 + i;
        float4 res = resbuf[i & 1];
        if (i < PPT-2)
            resbuf[i & 1] = __ldg((const float4*)(x + obase + (size_t)(p+2)*HW));

        // single LDS batch: 9 x LDS.128 covers both halves of this p
        uint4 wq[9];
        #pragma unroll
        for (int t = 0; t < 9; t++) wq[t] = s_w4[p*9 + t];   // warp-uniform

        int acc0 = 0, acc1 = 0, acc2 = 0, acc3 = 0;

        #pragma unroll
        for (int j = 0; j < NPIX; j++) {
            int part;
            {   // lo half
                unsigned w_[9];
                #pragma unroll
                for (int t = 0; t < 9; t++) {
                    const int ri = t / 3, ci = t % 3;
                    w_[t] = (mlo[ri][ci + j] ^ wq[t].x) & wq[t].y;
                }
                unsigned s0 = xor3(w_[0], w_[1], w_[2]), c0 = maj3(w_[0], w_[1], w_[2]);
                unsigned s1 = xor3(w_[3], w_[4], w_[5]), c1 = maj3(w_[3], w_[4], w_[5]);
                unsigned s2 = xor3(w_[6], w_[7], w_[8]), c2 = maj3(w_[6], w_[7], w_[8]);
                unsigned S  = xor3(s0, s1, s2), C  = maj3(s0, s1, s2);
                unsigned S2 = xor3(c0, c1, c2), C2 = maj3(c0, c1, c2);
                part = __popc(S) + 2*(__popc(C) + __popc(S2)) + 4*__popc(C2);
            }
            {   // hi half
                unsigned w_[9];
                #pragma unroll
                for (int t = 0; t < 9; t++) {
                    const int ri = t / 3, ci = t % 3;
                    w_[t] = (mhi[ri][ci + j] ^ wq[t].z) & wq[t].w;
                }
                unsigned s0 = xor3(w_[0], w_[1], w_[2]), c0 = maj3(w_[0], w_[1], w_[2]);
                unsigned s1 = xor3(w_[3], w_[4], w_[5]), c1 = maj3(w_[3], w_[4], w_[5]);
                unsigned s2 = xor3(w_[6], w_[7], w_[8]), c2 = maj3(w_[6], w_[7], w_[8]);
                unsigned S  = xor3(s0, s1, s2), C  = maj3(s0, s1, s2);
                unsigned S2 = xor3(c0, c1, c2), C2 = maj3(c0, c1, c2);
                part += __popc(S) + 2*(__popc(C) + __popc(S2)) + 4*__popc(C2);
            }
            if (j == 0) acc0 = part;
            else if (j == 1) acc1 = part;
            else if (j == 2) acc2 = part;
            else acc3 = part;
        }

        float4 e = s_epi[p];
        float A2 = 2.0f * e.x;
        float bM = fmaf(s_basef[caseM*Pp + p], -e.x, e.y);
        float bL = fmaf(s_basef[caseL*Pp + p], -e.x, e.y);
        float bR = fmaf(s_basef[caseR*Pp + p], -e.x, e.y);

        float4 o; float v;
        v = fmaf((float)acc0, A2, bL) + res.x; o.x = (v >= 0.f ? v : v*e.z) + e.w;
        v = fmaf((float)acc1, A2, bM) + res.y; o.y = (v >= 0.f ? v : v*e.z) + e.w;
        v = fmaf((float)acc2, A2, bM) + res.z; o.z = (v >= 0.f ? v : v*e.z) + e.w;
        v = fmaf((float)acc3, A2, bR) + res.w; o.w = (v >= 0.f ? v : v*e.z) + e.w;
        *(float4*)(out + obase + (size_t)p*HW) = o;
    }
}

// ---------------- fixup: exact recompute for exact-zero activations ----------------
__global__ void fixup_kernel(const float* __restrict__ x,
                             const float* __restrict__ bias0,
                             const float* __restrict__ w,
                             float* __restrict__ out) {
    int cnt = g_zero_cnt;
    if (cnt > 4096) cnt = 4096;
    int nitems = cnt * 9 * Pp;
    for (int it = blockIdx.x*blockDim.x + threadIdx.x; it < nitems;
         it += gridDim.x*blockDim.x) {
        int zi  = it / (9*Pp);
        int rem = it % (9*Pp);
        int d   = rem / Pp;
        int p   = rem % Pp;
        int z   = g_zero_list[zi];
        int b   = z / CHW;
        int zr  = (z % CHW) % HW;
        int zh  = zr / Ww, zw = zr % Ww;
        int oh  = zh + (d/3) - 1;
        int ow  = zw + (d%3) - 1;
        if (oh < 0 || oh >= Hh || ow < 0 || ow >= Ww) continue;

        float conv = 0.f;
        const float* wp = w + p*(Cc*9);
        for (int c = 0; c < Cc; c++) {
            const float* xc = x + (size_t)b*CHW + (size_t)c*HW;
            float b0 = bias0[c];
            #pragma unroll
            for (int t = 0; t < 9; t++) {
                int ih = oh + t/3 - 1, iw = ow + t%3 - 1;
                if (ih < 0 || ih >= Hh || iw < 0 || iw >= Ww) continue;
                float v  = xc[ih*Ww + iw] + b0;
                float a  = (v  > 0.f) ? 1.f : ((v  < 0.f) ? -1.f : 0.f);
                float wv = wp[c*9 + t];
                float ws = (wv > 0.f) ? 1.f : ((wv < 0.f) ? -1.f : 0.f);
                conv += a * ws;
            }
        }
        float4 e = g_epi[p];
        size_t oi = (size_t)b*CHW + (size_t)p*HW + (size_t)oh*Ww + ow;
        float val = fmaf(conv, e.x, e.y) + x[oi];
        val = (val >= 0.f ? val : val*e.z) + e.w;
        out[oi] = val;
    }
}

// ---------------- launch ----------------
extern "C" void kernel_launch(void* const* d_in, const int* in_sizes, int n_in,
                              void* d_out, int out_size) {
    const float* x     = (const float*)d_in[0];
    const float* bias0 = (const float*)d_in[1];
    const float* w     = (const float*)d_in[2];
    const float* gamma = (const float*)d_in[3];
    const float* beta  = (const float*)d_in[4];
    const float* rmean = (const float*)d_in[5];
    const float* rvar  = (const float*)d_in[6];
    const float* bias1 = (const float*)d_in[7];
    const float* alpha = (const float*)d_in[8];
    const float* bias2 = (const float*)d_in[9];
    float* out = (float*)d_out;

    prep_kernel<<<Pp, 64>>>(w, gamma, beta, rmean, rvar, bias1, alpha, bias2);
    binarize_kernel<<<PIX/256, 256>>>(x, bias0);
    noop_kernel<<<1, 32>>>();
    conv_kernel<<<GROUPS/32, 128>>>(x, out);   // 4th launch -> ncu capture slot
    fixup_kernel<<<16, 256>>>(x, bias0, w, out);
}

// round 14
// speedup vs baseline: 1.0308x; 1.0308x over previous
#include <cuda_runtime.h>
#include <stdint.h>

#define Bn 64
#define Cc 64
#define Hh 56
#define Ww 56
#define Pp 64
#define HW (Hh*Ww)        // 3136
#define CHW (Cc*HW)       // 200704
#define PIX (Bn*HW)       // 200704
#define PADW 58
#define PADHW (58*58)     // 3364
#define NPIX 4
#define GPR (Ww/NPIX)     // 14
#define GROUPS (PIX/NPIX) // 50176  (= 32 * 1568 exactly)
#define NBLK 1568         // g-groups of 32 quads
#define PGRID 740         // persistent grid: 148 SM x 5 blocks
#define PSPLIT 4
#define PPT (Pp/PSPLIT)   // 16 output channels per thread

// ---- device scratch (statically zero-initialized; border of g_amask stays 0) ----
__device__ unsigned long long g_amask[Bn*PADHW];   // padded per-pixel sign masks (~1.7MB)
__device__ uint2  g_wlo[Pp*9];    // per (p,tap): (pw_lo, vm_lo)
__device__ uint2  g_whi[Pp*9];    // per (p,tap): (pw_hi, vm_hi)
__device__ float  g_basef[9*Pp];  // per (border-case, p): base constant (as float)
__device__ float4 g_epi[Pp];      // A=scale*inv, B=beta-mean*inv+bias1, alpha, bias2
__device__ int    g_zero_cnt;
__device__ int    g_zero_list[4096];

// ---------------- prep: one block per output channel p; ballot-built masks ----------------
__global__ void prep_kernel(const float* __restrict__ w,
                            const float* __restrict__ gamma,
                            const float* __restrict__ beta,
                            const float* __restrict__ rmean,
                            const float* __restrict__ rvar,
                            const float* __restrict__ bias1,
                            const float* __restrict__ alpha,
                            const float* __restrict__ bias2) {
    int p = blockIdx.x;
    int c = threadIdx.x;            // 0..63 (one input channel per thread)
    int lane = c & 31, half = c >> 5;
    if (p == 0 && c == 0) g_zero_cnt = 0;   // init (prep runs before binarize)

    __shared__ unsigned s_pw[2][9], s_vm[2][9];
    __shared__ float s_abs[64];

    const float* wp = w + (size_t)p*(Cc*9) + (size_t)c*9;
    float wv[9], sa = 0.f;
    #pragma unroll
    for (int t = 0; t < 9; t++) { wv[t] = __ldg(wp + t); sa += fabsf(wv[t]); }
    s_abs[c] = sa;
    #pragma unroll
    for (int t = 0; t < 9; t++) {
        unsigned bp = __ballot_sync(0xffffffffu, wv[t] > 0.f);
        unsigned bv = __ballot_sync(0xffffffffu, wv[t] != 0.f);
        if (lane == 0) { s_pw[half][t] = bp; s_vm[half][t] = bv; }
    }
    __syncthreads();
    if (c != 0) return;

    float sabs = 0.f;
    for (int i = 0; i < 64; i++) sabs += s_abs[i];
    float scale = sabs * (1.0f / (float)(Cc*9));

    int nv[9], ppw[9];
    #pragma unroll
    for (int t = 0; t < 9; t++) {
        uint2 vlo, vhi;
        vlo.x = s_pw[0][t]; vlo.y = s_vm[0][t];
        vhi.x = s_pw[1][t]; vhi.y = s_vm[1][t];
        g_wlo[p*9 + t] = vlo;
        g_whi[p*9 + t] = vhi;
        nv[t]  = __popc(vlo.y) + __popc(vhi.y);
        ppw[t] = __popc(vlo.x) + __popc(vhi.x);
    }
    // conv = 2*acc - base[case]; valid tap contributes nv, padded tap 2*popc(pw)
    #pragma unroll
    for (int cs = 0; cs < 9; cs++) {
        int ch = cs / 3, cw = cs % 3;
        int base = 0;
        #pragma unroll
        for (int t = 0; t < 9; t++) {
            int kh = t / 3, kw = t % 3;
            bool invalid = (ch==0 && kh==0) || (ch==2 && kh==2) ||
                           (cw==0 && kw==0) || (cw==2 && kw==2);
            base += invalid ? 2*ppw[t] : nv[t];
        }
        g_basef[cs*Pp + p] = (float)base;
    }
    float inv = gamma[p] / sqrtf(rvar[p] + 1e-5f);
    float4 e;
    e.x = scale * inv;
    e.y = beta[p] - rmean[p]*inv + bias1[p];
    e.z = alpha[p];
    e.w = bias2[p];
    g_epi[p] = e;
}

// ---------------- binarize: 4 threads per pixel-quad (16 channels each) ----------------
__global__ __launch_bounds__(256)
void binarize_kernel(const float* __restrict__ x, const float* __restrict__ bias0) {
    int tid  = blockIdx.x*blockDim.x + threadIdx.x;   // 0 .. PIX-1 exactly
    int quad = tid >> 2;
    int cg   = tid & 3;                               // channel group of 16
    int b  = quad / (HW/4);
    int r4 = quad % (HW/4);
    int r  = r4 * 4;
    const float4* xp = (const float4*)(x + (size_t)b*CHW) + r4 + (size_t)(cg*16)*(HW/4);

    unsigned bits[4] = {0,0,0,0};
    bool anyzero = false;
    #pragma unroll
    for (int i = 0; i < 16; i++) {
        float bb = __ldg(bias0 + cg*16 + i);
        float4 v = __ldg(xp + (size_t)i*(HW/4));
        v.x += bb; v.y += bb; v.z += bb; v.w += bb;
        anyzero |= (v.x == 0.f) | (v.y == 0.f) | (v.z == 0.f) | (v.w == 0.f);
        bits[0] |= (unsigned)(v.x < 0.f) << i;
        bits[1] |= (unsigned)(v.y < 0.f) << i;
        bits[2] |= (unsigned)(v.z < 0.f) << i;
        bits[3] |= (unsigned)(v.w < 0.f) << i;
    }
    if (anyzero) {  // rare exact-zero: queue exact indices for fixup
        #pragma unroll
        for (int i = 0; i < 16; i++) {
            int c = cg*16 + i;
            float bb = __ldg(bias0 + c);
            float4 v = __ldg(xp + (size_t)i*(HW/4));
            float vv[4] = {v.x+bb, v.y+bb, v.z+bb, v.w+bb};
            for (int k = 0; k < 4; k++)
                if (vv[k] == 0.f) {
                    int s = atomicAdd(&g_zero_cnt, 1);
                    if (s < 4096) g_zero_list[s] = b*CHW + c*HW + (r+k);
                }
        }
    }
    unsigned sh = (cg & 1) * 16;
    int h = r / Ww, w_ = r % Ww;   // 4 pixels in same row (Ww % 4 == 0)
    unsigned long long* dst = g_amask + b*PADHW + (h+1)*PADW + (w_+1);
    #pragma unroll
    for (int k = 0; k < 4; k++) {
        unsigned v = bits[k] << sh;
        v |= __shfl_xor_sync(0xffffffffu, v, 1);        // merge halves of the 32-bit word
        unsigned other = __shfl_xor_sync(0xffffffffu, v, 2); // lo <-> hi exchange
        if (cg == 0)
            dst[k] = (unsigned long long)v | ((unsigned long long)other << 32);
    }
}

__global__ void noop_kernel() {}   // keeps conv in the profiled 4th launch slot

__device__ __forceinline__ unsigned xor3(unsigned a, unsigned b, unsigned c) {
    return a ^ b ^ c;
}
__device__ __forceinline__ unsigned maj3(unsigned a, unsigned b, unsigned c) {
    return (a & b) | (c & (a | b));
}

// ---------------- conv: persistent CSA popcount ternary conv, prefetch-2 ----------------
// Persistent grid of 740 blocks (1 clean wave at 5/SM); each block strides over g-groups.
__global__ __launch_bounds__(128, 5)
void conv_kernel(const float* __restrict__ x, float* __restrict__ out) {
    __shared__ uint2  s_wlo[Pp*9];
    __shared__ uint2  s_whi[Pp*9];
    __shared__ float  s_basef[9*Pp];
    __shared__ float4 s_epi[Pp];
    for (int i = threadIdx.x; i < Pp*9; i += blockDim.x) { s_wlo[i] = g_wlo[i]; s_whi[i] = g_whi[i]; }
    for (int i = threadIdx.x; i < 9*Pp; i += blockDim.x) s_basef[i] = g_basef[i];
    for (int i = threadIdx.x; i < Pp;   i += blockDim.x) s_epi[i]   = g_epi[i];
    __syncthreads();

    int lane = threadIdx.x & 31;
    int psub = threadIdx.x >> 5;            // warp id = output-channel subset
    int p0 = psub * PPT;

    for (int blk = blockIdx.x; blk < NBLK; blk += PGRID) {
        int g = blk * 32 + lane;            // pixel-quad
        int b  = g / (Hh*GPR);
        int r  = g % (Hh*GPR);
        int h  = r / GPR;
        int w0 = (r % GPR) * NPIX;

        // 3 rows x 6 cols of padded neighbor masks, split into 32-bit halves
        unsigned mlo[3][6], mhi[3][6];
        const unsigned long long* am = g_amask + b*PADHW;
        #pragma unroll
        for (int ri = 0; ri < 3; ri++)
            #pragma unroll
            for (int ci = 0; ci < 6; ci++) {
                unsigned long long v = __ldg(am + (h+ri)*PADW + (w0+ci));
                mlo[ri][ci] = (unsigned)v;
                mhi[ri][ci] = (unsigned)(v >> 32);
            }

        int ch    = (h == 0) ? 0 : ((h == Hh-1) ? 2 : 1);
        int caseM = ch*3 + 1;
        int caseL = ch*3 + ((w0 == 0) ? 0 : 1);
        int caseR = ch*3 + ((w0 + NPIX - 1 == Ww-1) ? 2 : 1);

        size_t obase = (size_t)b*CHW + (size_t)h*Ww + w0;

        // residual prefetch ring, distance 2
        float4 resbuf[2];
        resbuf[0] = __ldg((const float4*)(x + obase + (size_t)(p0+0)*HW));
        resbuf[1] = __ldg((const float4*)(x + obase + (size_t)(p0+1)*HW));

        #pragma unroll 2
        for (int i = 0; i < PPT; i++) {
            int p = p0 + i;
            float4 res = resbuf[i & 1];
            if (i < PPT-2)
                resbuf[i & 1] = __ldg((const float4*)(x + obase + (size_t)(p+2)*HW));

            int acc0 = 0, acc1 = 0, acc2 = 0, acc3 = 0;

            #pragma unroll
            for (int half = 0; half < 2; half++) {
                const uint2* sw = half ? (s_whi + p*9) : (s_wlo + p*9);
                uint2 wr[9];
                #pragma unroll
                for (int t = 0; t < 9; t++) wr[t] = sw[t];   // warp-uniform LDS.64
                const unsigned (*m)[6] = half ? mhi : mlo;

                #pragma unroll
                for (int j = 0; j < NPIX; j++) {
                    unsigned w_[9];
                    #pragma unroll
                    for (int t = 0; t < 9; t++) {
                        const int ri = t / 3, ci = t % 3;
                        w_[t] = (m[ri][ci + j] ^ wr[t].x) & wr[t].y;   // single LOP3
                    }
                    // 2-level CSA tree: 9 popcs -> 4 popcs
                    unsigned s0 = xor3(w_[0], w_[1], w_[2]), c0 = maj3(w_[0], w_[1], w_[2]);
                    unsigned s1 = xor3(w_[3], w_[4], w_[5]), c1 = maj3(w_[3], w_[4], w_[5]);
                    unsigned s2 = xor3(w_[6], w_[7], w_[8]), c2 = maj3(w_[6], w_[7], w_[8]);
                    unsigned S  = xor3(s0, s1, s2), C  = maj3(s0, s1, s2);
                    unsigned S2 = xor3(c0, c1, c2), C2 = maj3(c0, c1, c2);
                    int part = __popc(S) + 2*(__popc(C) + __popc(S2)) + 4*__popc(C2);
                    if (j == 0) acc0 += part;
                    else if (j == 1) acc1 += part;
                    else if (j == 2) acc2 += part;
                    else acc3 += part;
                }
            }

            float4 e = s_epi[p];
            float A2 = 2.0f * e.x;
            float bM = fmaf(s_basef[caseM*Pp + p], -e.x, e.y);
            float bL = fmaf(s_basef[caseL*Pp + p], -e.x, e.y);
            float bR = fmaf(s_basef[caseR*Pp + p], -e.x, e.y);

            float4 o; float v;
            v = fmaf((float)acc0, A2, bL) + res.x; o.x = (v >= 0.f ? v : v*e.z) + e.w;
            v = fmaf((float)acc1, A2, bM) + res.y; o.y = (v >= 0.f ? v : v*e.z) + e.w;
            v = fmaf((float)acc2, A2, bM) + res.z; o.z = (v >= 0.f ? v : v*e.z) + e.w;
            v = fmaf((float)acc3, A2, bR) + res.w; o.w = (v >= 0.f ? v : v*e.z) + e.w;
            *(float4*)(out + obase + (size_t)p*HW) = o;
        }
    }
}

// ---------------- fixup: exact recompute for exact-zero activations ----------------
__global__ void fixup_kernel(const float* __restrict__ x,
                             const float* __restrict__ bias0,
                             const float* __restrict__ w,
                             float* __restrict__ out) {
    int cnt = g_zero_cnt;
    if (cnt > 4096) cnt = 4096;
    int nitems = cnt * 9 * Pp;
    for (int it = blockIdx.x*blockDim.x + threadIdx.x; it < nitems;
         it += gridDim.x*blockDim.x) {
        int zi  = it / (9*Pp);
        int rem = it % (9*Pp);
        int d   = rem / Pp;
        int p   = rem % Pp;
        int z   = g_zero_list[zi];
        int b   = z / CHW;
        int zr  = (z % CHW) % HW;
        int zh  = zr / Ww, zw = zr % Ww;
        int oh  = zh + (d/3) - 1;
        int ow  = zw + (d%3) - 1;
        if (oh < 0 || oh >= Hh || ow < 0 || ow >= Ww) continue;

        float conv = 0.f;
        const float* wp = w + p*(Cc*9);
        for (int c = 0; c < Cc; c++) {
            const float* xc = x + (size_t)b*CHW + (size_t)c*HW;
            float b0 = bias0[c];
            #pragma unroll
            for (int t = 0; t < 9; t++) {
                int ih = oh + t/3 - 1, iw = ow + t%3 - 1;
                if (ih < 0 || ih >= Hh || iw < 0 || iw >= Ww) continue;
                float v  = xc[ih*Ww + iw] + b0;
                float a  = (v  > 0.f) ? 1.f : ((v  < 0.f) ? -1.f : 0.f);
                float wv = wp[c*9 + t];
                float ws = (wv > 0.f) ? 1.f : ((wv < 0.f) ? -1.f : 0.f);
                conv += a * ws;
            }
        }
        float4 e = g_epi[p];
        size_t oi = (size_t)b*CHW + (size_t)p*HW + (size_t)oh*Ww + ow;
        float val = fmaf(conv, e.x, e.y) + x[oi];
        val = (val >= 0.f ? val : val*e.z) + e.w;
        out[oi] = val;
    }
}

// ---------------- launch ----------------
extern "C" void kernel_launch(void* const* d_in, const int* in_sizes, int n_in,
                              void* d_out, int out_size) {
    const float* x     = (const float*)d_in[0];
    const float* bias0 = (const float*)d_in[1];
    const float* w     = (const float*)d_in[2];
    const float* gamma = (const float*)d_in[3];
    const float* beta  = (const float*)d_in[4];
    const float* rmean = (const float*)d_in[5];
    const float* rvar  = (const float*)d_in[6];
    const float* bias1 = (const float*)d_in[7];
    const float* alpha = (const float*)d_in[8];
    const float* bias2 = (const float*)d_in[9];
    float* out = (float*)d_out;

    prep_kernel<<<Pp, 64>>>(w, gamma, beta, rmean, rvar, bias1, alpha, bias2);
    binarize_kernel<<<PIX/256, 256>>>(x, bias0);
    noop_kernel<<<1, 32>>>();
    conv_kernel<<<PGRID, 128>>>(x, out);   // 4th launch -> ncu capture slot
    fixup_kernel<<<16, 256>>>(x, bias0, w, out);
}

// round 15
// speedup vs baseline: 1.0811x; 1.0487x over previous
#include <cuda_runtime.h>
#include <stdint.h>

#define Bn 64
#define Cc 64
#define Hh 56
#define Ww 56
#define Pp 64
#define HW (Hh*Ww)        // 3136
#define CHW (Cc*HW)       // 200704
#define PIX (Bn*HW)       // 200704
#define PADW 58
#define PADHW (58*58)     // 3364
#define NPIX 4
#define GPR (Ww/NPIX)     // 14
#define GROUPS (PIX/NPIX) // 50176  (= 32 * 1568 exactly)
#define PSPLIT 4
#define PPT (Pp/PSPLIT)   // 16 output channels per thread

// ---- device scratch (statically zero-initialized; border of g_amask stays 0) ----
__device__ unsigned long long g_amask[Bn*PADHW];   // padded per-pixel sign masks (~1.7MB)
__device__ uint2  g_wlo[Pp*9];    // per (p,tap): (pw_lo, vm_lo)
__device__ uint2  g_whi[Pp*9];    // per (p,tap): (pw_hi, vm_hi)
__device__ float  g_basef[9*Pp];  // per (border-case, p): base constant (as float)
__device__ float4 g_epi[Pp];      // A=scale*inv, B=beta-mean*inv+bias1, alpha, bias2
__device__ int    g_zero_cnt;
__device__ int    g_zero_list[4096];

// ---------------- prep: one block per output channel p; ballot-built masks ----------------
__global__ void prep_kernel(const float* __restrict__ w,
                            const float* __restrict__ gamma,
                            const float* __restrict__ beta,
                            const float* __restrict__ rmean,
                            const float* __restrict__ rvar,
                            const float* __restrict__ bias1,
                            const float* __restrict__ alpha,
                            const float* __restrict__ bias2) {
    int p = blockIdx.x;
    int c = threadIdx.x;            // 0..63 (one input channel per thread)
    int lane = c & 31, half = c >> 5;
    if (p == 0 && c == 0) g_zero_cnt = 0;   // init (prep runs before binarize)

    __shared__ unsigned s_pw[2][9], s_vm[2][9];
    __shared__ float s_abs[64];

    const float* wp = w + (size_t)p*(Cc*9) + (size_t)c*9;
    float wv[9], sa = 0.f;
    #pragma unroll
    for (int t = 0; t < 9; t++) { wv[t] = __ldg(wp + t); sa += fabsf(wv[t]); }
    s_abs[c] = sa;
    #pragma unroll
    for (int t = 0; t < 9; t++) {
        unsigned bp = __ballot_sync(0xffffffffu, wv[t] > 0.f);
        unsigned bv = __ballot_sync(0xffffffffu, wv[t] != 0.f);
        if (lane == 0) { s_pw[half][t] = bp; s_vm[half][t] = bv; }
    }
    __syncthreads();
    if (c != 0) return;

    float sabs = 0.f;
    for (int i = 0; i < 64; i++) sabs += s_abs[i];
    float scale = sabs * (1.0f / (float)(Cc*9));

    int nv[9], ppw[9];
    #pragma unroll
    for (int t = 0; t < 9; t++) {
        uint2 vlo, vhi;
        vlo.x = s_pw[0][t]; vlo.y = s_vm[0][t];
        vhi.x = s_pw[1][t]; vhi.y = s_vm[1][t];
        g_wlo[p*9 + t] = vlo;
        g_whi[p*9 + t] = vhi;
        nv[t]  = __popc(vlo.y) + __popc(vhi.y);
        ppw[t] = __popc(vlo.x) + __popc(vhi.x);
    }
    // conv = 2*acc - base[case]; valid tap contributes nv, padded tap 2*popc(pw)
    #pragma unroll
    for (int cs = 0; cs < 9; cs++) {
        int ch = cs / 3, cw = cs % 3;
        int base = 0;
        #pragma unroll
        for (int t = 0; t < 9; t++) {
            int kh = t / 3, kw = t % 3;
            bool invalid = (ch==0 && kh==0) || (ch==2 && kh==2) ||
                           (cw==0 && kw==0) || (cw==2 && kw==2);
            base += invalid ? 2*ppw[t] : nv[t];
        }
        g_basef[cs*Pp + p] = (float)base;
    }
    float inv = gamma[p] / sqrtf(rvar[p] + 1e-5f);
    float4 e;
    e.x = scale * inv;
    e.y = beta[p] - rmean[p]*inv + bias1[p];
    e.z = alpha[p];
    e.w = bias2[p];
    g_epi[p] = e;
}

// ---------------- binarize: 8 threads per pixel-quad (8 channels each) ----------------
// thread = (quad, cg of 8 channels); 3-step shfl_xor OR-reduce builds the 64-bit mask.
__global__ __launch_bounds__(256)
void binarize_kernel(const float* __restrict__ x, const float* __restrict__ bias0) {
    int tid  = blockIdx.x*blockDim.x + threadIdx.x;   // 0 .. 2*PIX-1 exactly
    int quad = tid >> 3;
    int cg   = tid & 7;                               // channel group of 8
    int b  = quad / (HW/4);
    int r4 = quad % (HW/4);
    int r  = r4 * 4;
    const float4* xp = (const float4*)(x + (size_t)b*CHW) + r4 + (size_t)(cg*8)*(HW/4);

    unsigned bits[4] = {0,0,0,0};
    bool anyzero = false;
    #pragma unroll
    for (int i = 0; i < 8; i++) {
        float bb = __ldg(bias0 + cg*8 + i);
        float4 v = __ldg(xp + (size_t)i*(HW/4));
        v.x += bb; v.y += bb; v.z += bb; v.w += bb;
        anyzero |= (v.x == 0.f) | (v.y == 0.f) | (v.z == 0.f) | (v.w == 0.f);
        bits[0] |= (unsigned)(v.x < 0.f) << i;
        bits[1] |= (unsigned)(v.y < 0.f) << i;
        bits[2] |= (unsigned)(v.z < 0.f) << i;
        bits[3] |= (unsigned)(v.w < 0.f) << i;
    }
    if (anyzero) {  // rare exact-zero: queue exact indices for fixup
        #pragma unroll
        for (int i = 0; i < 8; i++) {
            int c = cg*8 + i;
            float bb = __ldg(bias0 + c);
            float4 v = __ldg(xp + (size_t)i*(HW/4));
            float vv[4] = {v.x+bb, v.y+bb, v.z+bb, v.w+bb};
            for (int k = 0; k < 4; k++)
                if (vv[k] == 0.f) {
                    int s = atomicAdd(&g_zero_cnt, 1);
                    if (s < 4096) g_zero_list[s] = b*CHW + c*HW + (r+k);
                }
        }
    }
    // cg 0..3 -> lo word bytes 0..3; cg 4..7 -> hi word bytes 0..3
    unsigned sh = (cg & 3) * 8;
    int h = r / Ww, w_ = r % Ww;   // 4 pixels in same row (Ww % 4 == 0)
    unsigned long long* dst = g_amask + b*PADHW + (h+1)*PADW + (w_+1);
    #pragma unroll
    for (int k = 0; k < 4; k++) {
        unsigned v = bits[k] << sh;
        v |= __shfl_xor_sync(0xffffffffu, v, 1);   // merge byte pairs
        v |= __shfl_xor_sync(0xffffffffu, v, 2);   // full 32-bit word per 4-lane group
        unsigned other = __shfl_xor_sync(0xffffffffu, v, 4);  // lo <-> hi exchange
        if (cg == 0)
            dst[k] = (unsigned long long)v | ((unsigned long long)other << 32);
    }
}

__global__ void noop_kernel() {}   // keeps conv in the profiled 4th launch slot

__device__ __forceinline__ unsigned xor3(unsigned a, unsigned b, unsigned c) {
    return a ^ b ^ c;
}
__device__ __forceinline__ unsigned maj3(unsigned a, unsigned b, unsigned c) {
    return (a & b) | (c & (a | b));
}

// ---------------- conv: CSA popcount ternary conv, prefetch-distance-2 residuals ----------------
// Block = 4 warps; warp = psub (16 output channels), lane = pixel-quad. (R12-proven config)
__global__ __launch_bounds__(128, 5)
void conv_kernel(const float* __restrict__ x, float* __restrict__ out) {
    __shared__ uint2  s_wlo[Pp*9];
    __shared__ uint2  s_whi[Pp*9];
    __shared__ float  s_basef[9*Pp];
    __shared__ float4 s_epi[Pp];
    for (int i = threadIdx.x; i < Pp*9; i += blockDim.x) { s_wlo[i] = g_wlo[i]; s_whi[i] = g_whi[i]; }
    for (int i = threadIdx.x; i < 9*Pp; i += blockDim.x) s_basef[i] = g_basef[i];
    for (int i = threadIdx.x; i < Pp;   i += blockDim.x) s_epi[i]   = g_epi[i];
    __syncthreads();

    int lane = threadIdx.x & 31;
    int psub = threadIdx.x >> 5;            // warp id = output-channel subset
    int g    = blockIdx.x * 32 + lane;      // pixel-quad (grid exact: 1568*32 = GROUPS)
    int b  = g / (Hh*GPR);
    int r  = g % (Hh*GPR);
    int h  = r / GPR;
    int w0 = (r % GPR) * NPIX;

    // 3 rows x 6 cols of padded neighbor masks, split into 32-bit halves
    unsigned mlo[3][6], mhi[3][6];
    const unsigned long long* am = g_amask + b*PADHW;
    #pragma unroll
    for (int ri = 0; ri < 3; ri++)
        #pragma unroll
        for (int ci = 0; ci < 6; ci++) {
            unsigned long long v = __ldg(am + (h+ri)*PADW + (w0+ci));
            mlo[ri][ci] = (unsigned)v;
            mhi[ri][ci] = (unsigned)(v >> 32);
        }

    int ch    = (h == 0) ? 0 : ((h == Hh-1) ? 2 : 1);
    int caseM = ch*3 + 1;
    int caseL = ch*3 + ((w0 == 0) ? 0 : 1);
    int caseR = ch*3 + ((w0 + NPIX - 1 == Ww-1) ? 2 : 1);

    size_t obase = (size_t)b*CHW + (size_t)h*Ww + w0;
    int p0 = psub * PPT;

    // residual prefetch ring, distance 2
    float4 resbuf[2];
    resbuf[0] = __ldg((const float4*)(x + obase + (size_t)(p0+0)*HW));
    resbuf[1] = __ldg((const float4*)(x + obase + (size_t)(p0+1)*HW));

    #pragma unroll 2
    for (int i = 0; i < PPT; i++) {
        int p = p0 + i;
        float4 res = resbuf[i & 1];
        if (i < PPT-2)
            resbuf[i & 1] = __ldg((const float4*)(x + obase + (size_t)(p+2)*HW));

        int acc0 = 0, acc1 = 0, acc2 = 0, acc3 = 0;

        #pragma unroll
        for (int half = 0; half < 2; half++) {
            const uint2* sw = half ? (s_whi + p*9) : (s_wlo + p*9);
            uint2 wr[9];
            #pragma unroll
            for (int t = 0; t < 9; t++) wr[t] = sw[t];   // warp-uniform LDS.64
            const unsigned (*m)[6] = half ? mhi : mlo;

            #pragma unroll
            for (int j = 0; j < NPIX; j++) {
                // 9 tap-words for this pixel
                unsigned w_[9];
                #pragma unroll
                for (int t = 0; t < 9; t++) {
                    const int ri = t / 3, ci = t % 3;
                    w_[t] = (m[ri][ci + j] ^ wr[t].x) & wr[t].y;   // single LOP3
                }
                // 2-level CSA tree: 9 popcs -> 4 popcs
                unsigned s0 = xor3(w_[0], w_[1], w_[2]), c0 = maj3(w_[0], w_[1], w_[2]);
                unsigned s1 = xor3(w_[3], w_[4], w_[5]), c1 = maj3(w_[3], w_[4], w_[5]);
                unsigned s2 = xor3(w_[6], w_[7], w_[8]), c2 = maj3(w_[6], w_[7], w_[8]);
                unsigned S  = xor3(s0, s1, s2), C  = maj3(s0, s1, s2);
                unsigned S2 = xor3(c0, c1, c2), C2 = maj3(c0, c1, c2);
                int part = __popc(S) + 2*(__popc(C) + __popc(S2)) + 4*__popc(C2);
                if (j == 0) acc0 += part;
                else if (j == 1) acc1 += part;
                else if (j == 2) acc2 += part;
                else acc3 += part;
            }
        }

        float4 e = s_epi[p];
        float A2 = 2.0f * e.x;
        float bM = fmaf(s_basef[caseM*Pp + p], -e.x, e.y);
        float bL = fmaf(s_basef[caseL*Pp + p], -e.x, e.y);
        float bR = fmaf(s_basef[caseR*Pp + p], -e.x, e.y);

        float4 o; float v;
        v = fmaf((float)acc0, A2, bL) + res.x; o.x = (v >= 0.f ? v : v*e.z) + e.w;
        v = fmaf((float)acc1, A2, bM) + res.y; o.y = (v >= 0.f ? v : v*e.z) + e.w;
        v = fmaf((float)acc2, A2, bM) + res.z; o.z = (v >= 0.f ? v : v*e.z) + e.w;
        v = fmaf((float)acc3, A2, bR) + res.w; o.w = (v >= 0.f ? v : v*e.z) + e.w;
        *(float4*)(out + obase + (size_t)p*HW) = o;
    }
}

// ---------------- fixup: exact recompute for exact-zero activations ----------------
__global__ void fixup_kernel(const float* __restrict__ x,
                             const float* __restrict__ bias0,
                             const float* __restrict__ w,
                             float* __restrict__ out) {
    int cnt = g_zero_cnt;
    if (cnt > 4096) cnt = 4096;
    int nitems = cnt * 9 * Pp;
    for (int it = blockIdx.x*blockDim.x + threadIdx.x; it < nitems;
         it += gridDim.x*blockDim.x) {
        int zi  = it / (9*Pp);
        int rem = it % (9*Pp);
        int d   = rem / Pp;
        int p   = rem % Pp;
        int z   = g_zero_list[zi];
        int b   = z / CHW;
        int zr  = (z % CHW) % HW;
        int zh  = zr / Ww, zw = zr % Ww;
        int oh  = zh + (d/3) - 1;
        int ow  = zw + (d%3) - 1;
        if (oh < 0 || oh >= Hh || ow < 0 || ow >= Ww) continue;

        float conv = 0.f;
        const float* wp = w + p*(Cc*9);
        for (int c = 0; c < Cc; c++) {
            const float* xc = x + (size_t)b*CHW + (size_t)c*HW;
            float b0 = bias0[c];
            #pragma unroll
            for (int t = 0; t < 9; t++) {
                int ih = oh + t/3 - 1, iw = ow + t%3 - 1;
                if (ih < 0 || ih >= Hh || iw < 0 || iw >= Ww) continue;
                float v  = xc[ih*Ww + iw] + b0;
                float a  = (v  > 0.f) ? 1.f : ((v  < 0.f) ? -1.f : 0.f);
                float wv = wp[c*9 + t];
                float ws = (wv > 0.f) ? 1.f : ((wv < 0.f) ? -1.f : 0.f);
                conv += a * ws;
            }
        }
        float4 e = g_epi[p];
        size_t oi = (size_t)b*CHW + (size_t)p*HW + (size_t)oh*Ww + ow;
        float val = fmaf(conv, e.x, e.y) + x[oi];
        val = (val >= 0.f ? val : val*e.z) + e.w;
        out[oi] = val;
    }
}

// ---------------- launch ----------------
extern "C" void kernel_launch(void* const* d_in, const int* in_sizes, int n_in,
                              void* d_out, int out_size) {
    const float* x     = (const float*)d_in[0];
    const float* bias0 = (const float*)d_in[1];
    const float* w     = (const float*)d_in[2];
    const float* gamma = (const float*)d_in[3];
    const float* beta  = (const float*)d_in[4];
    const float* rmean = (const float*)d_in[5];
    const float* rvar  = (const float*)d_in[6];
    const float* bias1 = (const float*)d_in[7];
    const float* alpha = (const float*)d_in[8];
    const float* bias2 = (const float*)d_in[9];
    float* out = (float*)d_out;

    prep_kernel<<<Pp, 64>>>(w, gamma, beta, rmean, rvar, bias1, alpha, bias2);
    binarize_kernel<<<2*PIX/256, 256>>>(x, bias0);
    noop_kernel<<<1, 32>>>();
    conv_kernel<<<GROUPS/32, 128>>>(x, out);   // 4th launch -> ncu capture slot
    fixup_kernel<<<16, 256>>>(x, bias0, w, out);
}

// round 16
// speedup vs baseline: 1.1770x; 1.0887x over previous
#include <cuda_runtime.h>
#include <stdint.h>

#define Bn 64
#define Cc 64
#define Hh 56
#define Ww 56
#define Pp 64
#define HW (Hh*Ww)        // 3136
#define CHW (Cc*HW)       // 200704
#define PIX (Bn*HW)       // 200704
#define PADW 58
#define PADHW (58*58)     // 3364
#define NPIX 4
#define GPR (Ww/NPIX)     // 14
#define GROUPS (PIX/NPIX) // 50176  (= 32 * 1568 exactly)
#define PSPLIT 4
#define PPT (Pp/PSPLIT)   // 16 output channels per thread
#define WSTRIDE 10        // padded per-p weight stride (uint2 units; 80B -> 16B aligned)

// ---- device scratch (statically zero-initialized; border of g_amask stays 0) ----
__device__ unsigned long long g_amask[Bn*PADHW];   // padded per-pixel sign masks (~1.7MB)
__device__ uint2  g_wlo[Pp*WSTRIDE];  // per (p,tap): (pw_lo, vm_lo), padded stride 10
__device__ uint2  g_whi[Pp*WSTRIDE];  // per (p,tap): (pw_hi, vm_hi), padded stride 10
__device__ float  g_basef[9*Pp];      // per (border-case, p): base constant (as float)
__device__ float4 g_epi[Pp];          // A=scale*inv, B=beta-mean*inv+bias1, alpha, bias2
__device__ int    g_zero_cnt;
__device__ int    g_zero_list[4096];

// ---------------- prep: one block per output channel p; ballot-built masks ----------------
__global__ void prep_kernel(const float* __restrict__ w,
                            const float* __restrict__ gamma,
                            const float* __restrict__ beta,
                            const float* __restrict__ rmean,
                            const float* __restrict__ rvar,
                            const float* __restrict__ bias1,
                            const float* __restrict__ alpha,
                            const float* __restrict__ bias2) {
    int p = blockIdx.x;
    int c = threadIdx.x;            // 0..63 (one input channel per thread)
    int lane = c & 31, half = c >> 5;
    if (p == 0 && c == 0) g_zero_cnt = 0;   // init (prep runs before binarize)

    __shared__ unsigned s_pw[2][9], s_vm[2][9];
    __shared__ float s_abs[64];

    const float* wp = w + (size_t)p*(Cc*9) + (size_t)c*9;
    float wv[9], sa = 0.f;
    #pragma unroll
    for (int t = 0; t < 9; t++) { wv[t] = __ldg(wp + t); sa += fabsf(wv[t]); }
    s_abs[c] = sa;
    #pragma unroll
    for (int t = 0; t < 9; t++) {
        unsigned bp = __ballot_sync(0xffffffffu, wv[t] > 0.f);
        unsigned bv = __ballot_sync(0xffffffffu, wv[t] != 0.f);
        if (lane == 0) { s_pw[half][t] = bp; s_vm[half][t] = bv; }
    }
    __syncthreads();
    if (c != 0) return;

    float sabs = 0.f;
    for (int i = 0; i < 64; i++) sabs += s_abs[i];
    float scale = sabs * (1.0f / (float)(Cc*9));

    int nv[9], ppw[9];
    #pragma unroll
    for (int t = 0; t < 9; t++) {
        uint2 vlo, vhi;
        vlo.x = s_pw[0][t]; vlo.y = s_vm[0][t];
        vhi.x = s_pw[1][t]; vhi.y = s_vm[1][t];
        g_wlo[p*WSTRIDE + t] = vlo;
        g_whi[p*WSTRIDE + t] = vhi;
        nv[t]  = __popc(vlo.y) + __popc(vhi.y);
        ppw[t] = __popc(vlo.x) + __popc(vhi.x);
    }
    // pad tail so conv's bulk copy reads defined data
    g_wlo[p*WSTRIDE + 9] = make_uint2(0u, 0u);
    g_whi[p*WSTRIDE + 9] = make_uint2(0u, 0u);

    // conv = 2*acc - base[case]; valid tap contributes nv, padded tap 2*popc(pw)
    #pragma unroll
    for (int cs = 0; cs < 9; cs++) {
        int ch = cs / 3, cw = cs % 3;
        int base = 0;
        #pragma unroll
        for (int t = 0; t < 9; t++) {
            int kh = t / 3, kw = t % 3;
            bool invalid = (ch==0 && kh==0) || (ch==2 && kh==2) ||
                           (cw==0 && kw==0) || (cw==2 && kw==2);
            base += invalid ? 2*ppw[t] : nv[t];
        }
        g_basef[cs*Pp + p] = (float)base;
    }
    float inv = gamma[p] / sqrtf(rvar[p] + 1e-5f);
    float4 e;
    e.x = scale * inv;
    e.y = beta[p] - rmean[p]*inv + bias1[p];
    e.z = alpha[p];
    e.w = bias2[p];
    g_epi[p] = e;
}

// ---------------- binarize: 4 threads per pixel-quad (16 channels each) — R12 proven ----------------
__global__ __launch_bounds__(256)
void binarize_kernel(const float* __restrict__ x, const float* __restrict__ bias0) {
    int tid  = blockIdx.x*blockDim.x + threadIdx.x;   // 0 .. PIX-1 exactly
    int quad = tid >> 2;
    int cg   = tid & 3;                               // channel group of 16
    int b  = quad / (HW/4);
    int r4 = quad % (HW/4);
    int r  = r4 * 4;
    const float4* xp = (const float4*)(x + (size_t)b*CHW) + r4 + (size_t)(cg*16)*(HW/4);

    unsigned bits[4] = {0,0,0,0};
    bool anyzero = false;
    #pragma unroll
    for (int i = 0; i < 16; i++) {
        float bb = __ldg(bias0 + cg*16 + i);
        float4 v = __ldg(xp + (size_t)i*(HW/4));
        v.x += bb; v.y += bb; v.z += bb; v.w += bb;
        anyzero |= (v.x == 0.f) | (v.y == 0.f) | (v.z == 0.f) | (v.w == 0.f);
        bits[0] |= (unsigned)(v.x < 0.f) << i;
        bits[1] |= (unsigned)(v.y < 0.f) << i;
        bits[2] |= (unsigned)(v.z < 0.f) << i;
        bits[3] |= (unsigned)(v.w < 0.f) << i;
    }
    if (anyzero) {  // rare exact-zero: queue exact indices for fixup
        #pragma unroll
        for (int i = 0; i < 16; i++) {
            int c = cg*16 + i;
            float bb = __ldg(bias0 + c);
            float4 v = __ldg(xp + (size_t)i*(HW/4));
            float vv[4] = {v.x+bb, v.y+bb, v.z+bb, v.w+bb};
            for (int k = 0; k < 4; k++)
                if (vv[k] == 0.f) {
                    int s = atomicAdd(&g_zero_cnt, 1);
                    if (s < 4096) g_zero_list[s] = b*CHW + c*HW + (r+k);
                }
        }
    }
    unsigned sh = (cg & 1) * 16;
    int h = r / Ww, w_ = r % Ww;   // 4 pixels in same row (Ww % 4 == 0)
    unsigned long long* dst = g_amask + b*PADHW + (h+1)*PADW + (w_+1);
    #pragma unroll
    for (int k = 0; k < 4; k++) {
        unsigned v = bits[k] << sh;
        v |= __shfl_xor_sync(0xffffffffu, v, 1);        // merge halves of the 32-bit word
        unsigned other = __shfl_xor_sync(0xffffffffu, v, 2); // lo <-> hi exchange
        if (cg == 0)
            dst[k] = (unsigned long long)v | ((unsigned long long)other << 32);
    }
}

__device__ __forceinline__ unsigned xor3(unsigned a, unsigned b, unsigned c) {
    return a ^ b ^ c;
}
__device__ __forceinline__ unsigned maj3(unsigned a, unsigned b, unsigned c) {
    return (a & b) | (c & (a | b));
}

// load 9 uint2 weights (padded record) via 4x LDS.128 + 1x LDS.64
__device__ __forceinline__ void load_w9(const uint2* base, uint2 wr[9]) {
    const uint4* q = (const uint4*)base;     // 16B-aligned (stride 80B)
    uint4 a0 = q[0], a1 = q[1], a2 = q[2], a3 = q[3];
    wr[0].x = a0.x; wr[0].y = a0.y;  wr[1].x = a0.z; wr[1].y = a0.w;
    wr[2].x = a1.x; wr[2].y = a1.y;  wr[3].x = a1.z; wr[3].y = a1.w;
    wr[4].x = a2.x; wr[4].y = a2.y;  wr[5].x = a2.z; wr[5].y = a2.w;
    wr[6].x = a3.x; wr[6].y = a3.y;  wr[7].x = a3.z; wr[7].y = a3.w;
    wr[8] = base[8];
}

// ---------------- conv: CSA popcount ternary conv, prefetch-2, vectorized weight LDS ----------------
// Block = 4 warps; warp = psub (16 output channels), lane = pixel-quad. (R12-proven config)
__global__ __launch_bounds__(128, 5)
void conv_kernel(const float* __restrict__ x, float* __restrict__ out) {
    __shared__ uint2  s_wlo[Pp*WSTRIDE];
    __shared__ uint2  s_whi[Pp*WSTRIDE];
    __shared__ float  s_basef[9*Pp];
    __shared__ float4 s_epi[Pp];
    for (int i = threadIdx.x; i < Pp*WSTRIDE; i += blockDim.x) { s_wlo[i] = g_wlo[i]; s_whi[i] = g_whi[i]; }
    for (int i = threadIdx.x; i < 9*Pp; i += blockDim.x) s_basef[i] = g_basef[i];
    for (int i = threadIdx.x; i < Pp;   i += blockDim.x) s_epi[i]   = g_epi[i];
    __syncthreads();

    int lane = threadIdx.x & 31;
    int psub = threadIdx.x >> 5;            // warp id = output-channel subset
    int g    = blockIdx.x * 32 + lane;      // pixel-quad (grid exact: 1568*32 = GROUPS)
    int b  = g / (Hh*GPR);
    int r  = g % (Hh*GPR);
    int h  = r / GPR;
    int w0 = (r % GPR) * NPIX;

    // 3 rows x 6 cols of padded neighbor masks, split into 32-bit halves
    unsigned mlo[3][6], mhi[3][6];
    const unsigned long long* am = g_amask + b*PADHW;
    #pragma unroll
    for (int ri = 0; ri < 3; ri++)
        #pragma unroll
        for (int ci = 0; ci < 6; ci++) {
            unsigned long long v = __ldg(am + (h+ri)*PADW + (w0+ci));
            mlo[ri][ci] = (unsigned)v;
            mhi[ri][ci] = (unsigned)(v >> 32);
        }

    int ch    = (h == 0) ? 0 : ((h == Hh-1) ? 2 : 1);
    int caseM = ch*3 + 1;
    int caseL = ch*3 + ((w0 == 0) ? 0 : 1);
    int caseR = ch*3 + ((w0 + NPIX - 1 == Ww-1) ? 2 : 1);

    size_t obase = (size_t)b*CHW + (size_t)h*Ww + w0;
    int p0 = psub * PPT;

    // residual prefetch ring, distance 2
    float4 resbuf[2];
    resbuf[0] = __ldg((const float4*)(x + obase + (size_t)(p0+0)*HW));
    resbuf[1] = __ldg((const float4*)(x + obase + (size_t)(p0+1)*HW));

    #pragma unroll 2
    for (int i = 0; i < PPT; i++) {
        int p = p0 + i;
        float4 res = resbuf[i & 1];
        if (i < PPT-2)
            resbuf[i & 1] = __ldg((const float4*)(x + obase + (size_t)(p+2)*HW));

        int acc0 = 0, acc1 = 0, acc2 = 0, acc3 = 0;

        #pragma unroll
        for (int half = 0; half < 2; half++) {
            const uint2* sw = half ? (s_whi + p*WSTRIDE) : (s_wlo + p*WSTRIDE);
            uint2 wr[9];
            load_w9(sw, wr);                 // 4x LDS.128 + 1x LDS.64, warp-uniform
            const unsigned (*m)[6] = half ? mhi : mlo;

            #pragma unroll
            for (int j = 0; j < NPIX; j++) {
                // 9 tap-words for this pixel
                unsigned w_[9];
                #pragma unroll
                for (int t = 0; t < 9; t++) {
                    const int ri = t / 3, ci = t % 3;
                    w_[t] = (m[ri][ci + j] ^ wr[t].x) & wr[t].y;   // single LOP3
                }
                // 2-level CSA tree: 9 popcs -> 4 popcs
                unsigned s0 = xor3(w_[0], w_[1], w_[2]), c0 = maj3(w_[0], w_[1], w_[2]);
                unsigned s1 = xor3(w_[3], w_[4], w_[5]), c1 = maj3(w_[3], w_[4], w_[5]);
                unsigned s2 = xor3(w_[6], w_[7], w_[8]), c2 = maj3(w_[6], w_[7], w_[8]);
                unsigned S  = xor3(s0, s1, s2), C  = maj3(s0, s1, s2);
                unsigned S2 = xor3(c0, c1, c2), C2 = maj3(c0, c1, c2);
                int part = __popc(S) + 2*(__popc(C) + __popc(S2)) + 4*__popc(C2);
                if (j == 0) acc0 += part;
                else if (j == 1) acc1 += part;
                else if (j == 2) acc2 += part;
                else acc3 += part;
            }
        }

        float4 e = s_epi[p];
        float A2 = 2.0f * e.x;
        float bM = fmaf(s_basef[caseM*Pp + p], -e.x, e.y);
        float bL = fmaf(s_basef[caseL*Pp + p], -e.x, e.y);
        float bR = fmaf(s_basef[caseR*Pp + p], -e.x, e.y);

        float4 o; float v;
        v = fmaf((float)acc0, A2, bL) + res.x; o.x = (v >= 0.f ? v : v*e.z) + e.w;
        v = fmaf((float)acc1, A2, bM) + res.y; o.y = (v >= 0.f ? v : v*e.z) + e.w;
        v = fmaf((float)acc2, A2, bM) + res.z; o.z = (v >= 0.f ? v : v*e.z) + e.w;
        v = fmaf((float)acc3, A2, bR) + res.w; o.w = (v >= 0.f ? v : v*e.z) + e.w;
        *(float4*)(out + obase + (size_t)p*HW) = o;
    }
}

// ---------------- fixup: exact recompute for exact-zero activations ----------------
__global__ void fixup_kernel(const float* __restrict__ x,
                             const float* __restrict__ bias0,
                             const float* __restrict__ w,
                             float* __restrict__ out) {
    int cnt = g_zero_cnt;
    if (cnt > 4096) cnt = 4096;
    int nitems = cnt * 9 * Pp;
    for (int it = blockIdx.x*blockDim.x + threadIdx.x; it < nitems;
         it += gridDim.x*blockDim.x) {
        int zi  = it / (9*Pp);
        int rem = it % (9*Pp);
        int d   = rem / Pp;
        int p   = rem % Pp;
        int z   = g_zero_list[zi];
        int b   = z / CHW;
        int zr  = (z % CHW) % HW;
        int zh  = zr / Ww, zw = zr % Ww;
        int oh  = zh + (d/3) - 1;
        int ow  = zw + (d%3) - 1;
        if (oh < 0 || oh >= Hh || ow < 0 || ow >= Ww) continue;

        float conv = 0.f;
        const float* wp = w + p*(Cc*9);
        for (int c = 0; c < Cc; c++) {
            const float* xc = x + (size_t)b*CHW + (size_t)c*HW;
            float b0 = bias0[c];
            #pragma unroll
            for (int t = 0; t < 9; t++) {
                int ih = oh + t/3 - 1, iw = ow + t%3 - 1;
                if (ih < 0 || ih >= Hh || iw < 0 || iw >= Ww) continue;
                float v  = xc[ih*Ww + iw] + b0;
                float a  = (v  > 0.f) ? 1.f : ((v  < 0.f) ? -1.f : 0.f);
                float wv = wp[c*9 + t];
                float ws = (wv > 0.f) ? 1.f : ((wv < 0.f) ? -1.f : 0.f);
                conv += a * ws;
            }
        }
        float4 e = g_epi[p];
        size_t oi = (size_t)b*CHW + (size_t)p*HW + (size_t)oh*Ww + ow;
        float val = fmaf(conv, e.x, e.y) + x[oi];
        val = (val >= 0.f ? val : val*e.z) + e.w;
        out[oi] = val;
    }
}

// ---------------- launch ----------------
extern "C" void kernel_launch(void* const* d_in, const int* in_sizes, int n_in,
                              void* d_out, int out_size) {
    const float* x     = (const float*)d_in[0];
    const float* bias0 = (const float*)d_in[1];
    const float* w     = (const float*)d_in[2];
    const float* gamma = (const float*)d_in[3];
    const float* beta  = (const float*)d_in[4];
    const float* rmean = (const float*)d_in[5];
    const float* rvar  = (const float*)d_in[6];
    const float* bias1 = (const float*)d_in[7];
    const float* alpha = (const float*)d_in[8];
    const float* bias2 = (const float*)d_in[9];
    float* out = (float*)d_out;

    prep_kernel<<<Pp, 64>>>(w, gamma, beta, rmean, rvar, bias1, alpha, bias2);
    binarize_kernel<<<PIX/256, 256>>>(x, bias0);
    conv_kernel<<<GROUPS/32, 128>>>(x, out);
    fixup_kernel<<<16, 256>>>(x, bias0, w, out);
}